// round 3
// baseline (speedup 1.0000x reference)
#include <cuda_runtime.h>
#include <cuda_bf16.h>
#include <float.h>
#include <math.h>
#include <stdint.h>

// ---------------- problem constants ----------------
constexpr int   Bn   = 16;
constexpr int   Nn   = 33600;
constexpr int   Cc   = 80;
constexpr int   MAXN = 100;
constexpr float THR  = 0.05f;
constexpr float IOUT = 0.65f;

// histogram select constants
constexpr unsigned BASE   = 0x3D000000u;   // below bits(0.05)=0x3D4CCCCD
constexpr int      CHUNKB = 11;            // buckets per thread chunk
constexpr int      NCH    = 1024;          // chunks (= threads)
constexpr int      NB     = CHUNKB * NCH;  // 11264 buckets (covers all scores < 1.0)
constexpr int      CAP    = 1024;          // candidate capacity

// dynamic smem: hist[NB] | csum[NCH] | wsum[32] | cand[CAP] | sorted[128] | misc[4]
constexpr int SEL_SMEM = NB * 4 + NCH * 4 + 32 * 4 + CAP * 8 + 128 * 8 + 4 * 4;

// ---------------- device scratch ----------------
__device__ float g_scores[Bn * Nn];   // masked score: s if s>=THR else -FLT_MAX
__device__ int   g_labels[Bn * Nn];   // argmax class

// ---------------- kernel 1: sigmoid + max/argmax + score ----------------
__global__ void k_score(const float* __restrict__ cls,
                        const float* __restrict__ obj) {
    int t   = blockIdx.x * blockDim.x + threadIdx.x;
    int a   = t >> 2;
    int sub = t & 3;
    if (a >= Bn * Nn) return;

    const float4* p = reinterpret_cast<const float4*>(cls + (size_t)a * Cc + sub * 20);
    float mx = -FLT_MAX;
    int   mi = 0;
#pragma unroll
    for (int i = 0; i < 5; i++) {
        float4 v = p[i];
        int base = sub * 20 + i * 4;
        if (v.x > mx) { mx = v.x; mi = base; }
        if (v.y > mx) { mx = v.y; mi = base + 1; }
        if (v.z > mx) { mx = v.z; mi = base + 2; }
        if (v.w > mx) { mx = v.w; mi = base + 3; }
    }
#pragma unroll
    for (int off = 1; off < 4; off <<= 1) {
        float om  = __shfl_xor_sync(0xffffffffu, mx, off);
        int   omi = __shfl_xor_sync(0xffffffffu, mi, off);
        if (om > mx || (om == mx && omi < mi)) { mx = om; mi = omi; }
    }
    if (sub == 0) {
        float o = obj[a];
        float s = (1.0f / (1.0f + __expf(-mx))) * (1.0f / (1.0f + __expf(-o)));
        g_scores[a] = (s >= THR) ? s : -FLT_MAX;
        g_labels[a] = mi;
    }
}

// intra-warp inclusive suffix sum (sum over lanes [lane..31])
__device__ __forceinline__ unsigned warp_suffix_sum(unsigned v, int lane) {
#pragma unroll
    for (int o = 1; o < 32; o <<= 1) {
        unsigned u = __shfl_down_sync(0xffffffffu, v, o);
        if (lane + o < 32) v += u;
    }
    return v;
}

// ---------------- kernel 2: fused histogram-select top-100 + decode + NMS ----------------
__global__ void __launch_bounds__(1024, 1)
k_select_nms(const float* __restrict__ bbox,
             const float* __restrict__ priors,
             float* __restrict__ out,
             int write_keep) {
    extern __shared__ unsigned char sraw[];
    unsigned*           hist   = (unsigned*)sraw;                    // [NB]
    unsigned*           csum   = hist + NB;                          // [NCH] (later: suffix sums)
    unsigned*           wsum   = csum + NCH;                         // [32]
    unsigned long long* cand   = (unsigned long long*)(wsum + 32);   // [CAP]
    unsigned long long* sorted = cand + CAP;                         // [128]
    int*                misc   = (int*)(sorted + 128);               // [4]
    // NMS arrays alias the hist region (dead after threshold refine)
    float4* bx4 = (float4*)hist;          // [128]
    float*  ars = (float*)(bx4 + 128);    // [128]
    float*  sss = ars + 128;              // [128]
    int*    lls = (int*)(sss + 128);      // [128]

    int b    = blockIdx.x;
    int tid  = threadIdx.x;
    int lane = tid & 31;
    int wid  = tid >> 5;
    const float* sc = g_scores + (size_t)b * Nn;

    // --- A: zero histogram + misc ---
#pragma unroll
    for (int i = 0; i < CHUNKB; i++) hist[tid + i * NCH] = 0;
    if (tid < 4) misc[tid] = 0;
    __syncthreads();

    // --- B: histogram score bit-patterns ---
    for (int i = tid; i < Nn; i += 1024) {
        float s = sc[i];
        if (s >= THR) {
            unsigned bits = __float_as_uint(s);
            atomicAdd(&hist[(bits - BASE) >> 12], 1u);
        }
    }
    __syncthreads();

    // --- C: parallel suffix sums over 1024 chunk-sums ---
    unsigned cs = 0;
#pragma unroll
    for (int i = 0; i < CHUNKB; i++) cs += hist[tid * CHUNKB + i];
    unsigned suf = warp_suffix_sum(cs, lane);     // suffix within my warp
    if (lane == 0) wsum[wid] = suf;               // warp total
    __syncthreads();
    if (wid == 0) {
        unsigned wv = wsum[lane];
        wsum[lane] = warp_suffix_sum(wv, lane);   // inclusive suffix over warps
    }
    __syncthreads();
    unsigned suffTotal = suf + ((wid < 31) ? wsum[wid + 1] : 0u);
    csum[tid] = suffTotal;                        // csum[t] = # candidates in chunks >= t
    __syncthreads();

    // boundary chunk: suffix(c) >= MAXN and suffix(c+1) < MAXN
    if (suffTotal >= (unsigned)MAXN &&
        (tid == NCH - 1 || csum[tid + 1] < (unsigned)MAXN))
        misc[0] = tid;
    __syncthreads();

    // --- refine to bucket within boundary chunk (<=11 serial steps) ---
    if (tid == 0) {
        int c = misc[0];
        int cum = (c < NCH - 1) ? (int)csum[c + 1] : 0;
        int bstart = c * CHUNKB;
        int bb = bstart + CHUNKB - 1;
        for (; bb >= bstart; bb--) {
            cum += (int)hist[bb];
            if (cum >= MAXN) break;
        }
        misc[0] = (bb < bstart) ? bstart : bb;    // total<MAXN -> take everything
        misc[1] = 0;
    }
    __syncthreads();

    // --- D: compact candidates >= bucket boundary ---
    unsigned TB = BASE + ((unsigned)misc[0] << 12);
    for (int i = tid; i < Nn; i += 1024) {
        float s = sc[i];
        if (s >= THR) {
            unsigned bits = __float_as_uint(s);
            if (bits >= TB) {
                int pos = atomicAdd(&misc[1], 1);
                if (pos < CAP)
                    cand[pos] = ((unsigned long long)bits << 32) | (unsigned)(~i);
            }
        }
    }
    __syncthreads();
    int cnt = misc[1]; if (cnt > CAP) cnt = CAP;

    // --- E: exact ordering by rank (keys unique: idx in low bits) ---
    if (tid < 128) sorted[tid] = 0ull;            // sentinel
    unsigned long long mykey = 0ull;
    int rank = 0;
    if (tid < cnt) {
        mykey = cand[tid];
#pragma unroll 4
        for (int j = 0; j < cnt; j++) rank += (cand[j] > mykey);
    }
    __syncthreads();
    if (tid < cnt && rank < 128) sorted[rank] = mykey;
    __syncthreads();

    // --- F: warp 0 only: decode top-100 + greedy class-aware NMS + write ---
    if (wid != 0) return;

    float x1q[4], y1q[4], x2q[4], y2q[4], aq[4], sq[4];
    int   lq[4];
    unsigned kmask = 0;
#pragma unroll
    for (int q = 0; q < 4; q++) {
        int r = lane + 32 * q;
        x1q[q] = y1q[q] = x2q[q] = y2q[q] = aq[q] = sq[q] = 0.0f;
        lq[q] = -1;
        if (r < MAXN) {
            unsigned long long key = sorted[r];
            unsigned bits = (unsigned)(key >> 32);
            if (bits != 0u) {
                int idx = (int)(~(unsigned)(key & 0xffffffffu));
                float4 pr = reinterpret_cast<const float4*>(priors)[idx];
                float4 bp = reinterpret_cast<const float4*>(bbox)[(size_t)b * Nn + idx];
                float cx = bp.x * pr.z + pr.x;
                float cy = bp.y * pr.w + pr.y;
                float w  = __expf(bp.z) * pr.z;
                float h  = __expf(bp.w) * pr.w;
                x1q[q] = cx - 0.5f * w; y1q[q] = cy - 0.5f * h;
                x2q[q] = cx + 0.5f * w; y2q[q] = cy + 0.5f * h;
                aq[q]  = w * h;
                sq[q]  = __uint_as_float(bits);
                lq[q]  = g_labels[(size_t)b * Nn + idx];
                kmask |= (1u << q);
            }
        }
    }
    // publish boxes for broadcast reads
#pragma unroll
    for (int q = 0; q < 4; q++) {
        int r = lane + 32 * q;
        if (r < MAXN) {
            bx4[r] = make_float4(x1q[q], y1q[q], x2q[q], y2q[q]);
            ars[r] = aq[q];
            lls[r] = lq[q];
        }
    }
    __syncwarp();

    for (int i = 0; i < MAXN - 1; i++) {
        unsigned km = __shfl_sync(0xffffffffu, kmask, i & 31);
        bool kpi = (km >> (i >> 5)) & 1u;
        float4 bi = bx4[i];
        float  ai = ars[i];
        int    li = lls[i];
        if (kpi) {
#pragma unroll
            for (int q = 0; q < 4; q++) {
                int r = lane + 32 * q;
                if (((kmask >> q) & 1u) && r > i && lq[q] == li) {
                    float ix1 = fmaxf(x1q[q], bi.x);
                    float iy1 = fmaxf(y1q[q], bi.y);
                    float ix2 = fminf(x2q[q], bi.z);
                    float iy2 = fminf(y2q[q], bi.w);
                    float inter = fmaxf(ix2 - ix1, 0.0f) * fmaxf(iy2 - iy1, 0.0f);
                    float uni   = aq[q] + ai - inter;
                    if (inter / (uni + 1e-8f) >= IOUT) kmask &= ~(1u << q);
                }
            }
        }
        __syncwarp();
    }

#pragma unroll
    for (int q = 0; q < 4; q++) {
        int r = lane + 32 * q;
        if (r < MAXN) {
            float* row = out + ((size_t)b * MAXN + r) * 6;
            bool kept = (kmask >> q) & 1u;
            if (kept) {
                row[0] = x1q[q]; row[1] = y1q[q];
                row[2] = x2q[q]; row[3] = y2q[q];
                row[4] = sq[q];  row[5] = (float)lq[q];
            } else {
                row[0] = 0.0f; row[1] = 0.0f; row[2] = 0.0f; row[3] = 0.0f;
                row[4] = 0.0f; row[5] = -1.0f;
            }
            if (write_keep)
                out[(size_t)Bn * MAXN * 6 + b * MAXN + r] = kept ? 1.0f : 0.0f;
        }
    }
}

// ---------------- host launcher ----------------
extern "C" void kernel_launch(void* const* d_in, const int* in_sizes, int n_in,
                              void* d_out, int out_size) {
    const float* cls    = nullptr;
    const float* bbox   = nullptr;
    const float* obj    = nullptr;
    const float* priors = nullptr;
    for (int i = 0; i < n_in; i++) {
        int sz = in_sizes[i];
        if      (sz == Bn * Nn * Cc) cls    = (const float*)d_in[i];
        else if (sz == Bn * Nn * 4)  bbox   = (const float*)d_in[i];
        else if (sz == Bn * Nn)      obj    = (const float*)d_in[i];
        else if (sz == Nn * 4)       priors = (const float*)d_in[i];
    }
    float* out = (float*)d_out;
    int write_keep = (out_size >= Bn * MAXN * 6 + Bn * MAXN) ? 1 : 0;

    cudaFuncSetAttribute(k_select_nms, cudaFuncAttributeMaxDynamicSharedMemorySize, SEL_SMEM);

    int total_threads = Bn * Nn * 4;
    k_score<<<(total_threads + 255) / 256, 256>>>(cls, obj);
    k_select_nms<<<Bn, 1024, SEL_SMEM>>>(bbox, priors, out, write_keep);
}